// round 15
// baseline (speedup 1.0000x reference)
#include <cuda_runtime.h>

// AngularSymmetry B=16, M=64 — SINGLE fused kernel (1024 blocks x 256).
// Grid is single-wave by construction (1024 <= 148 SMs x 7 blocks/SM via
// launch_bounds(256,7)), so an in-grid spin barrier is deadlock-free.
//
// Phase 1 (threads 0..32 per block): compute 33 of the 33792 SD elements
//   (33792 = 1024 * 33 exactly; e = bi*33 + tid)
//   SD[b][m][k] = wgt*(g[(k+m)%64][k] + g[k][(k+m)%64]), m=0..32,
//   g = __expf(-4 d^2)*dc; wgt = 0.125 (m=0), 0.5 (m=32), 1 else.
// Barrier: threadfence + atomicAdd(prep_done); spin until 1024; threadfence.
// Phase 2: block (b,i) main loop — m = 4t+g+1 (t=0..7, g=tid>>6), diagonal
//   on g==0 (SD row0 x4) issued first; Sv LDG MLP-4 batches; vj/Fj LDS
//   double-buffered; raw rcp.approx divide; 1-word Cody-Waite cos;
//   packed f32x2 powers/accumulators/reduction.
// Replay reset: last block to finish resets both counters (all blocks have
//   already passed the barrier, so the reset races with nothing).

#define B_DIM 16
#define M_DIM 64
#define SD_STRIDE (33 * 64)     // 2112 floats per batch
#define SD_TOTAL (B_DIM * SD_STRIDE)   // 33792 = 1024 * 33
#define GRID_N 1024

__device__ float SD_buf[SD_TOTAL];
__device__ unsigned prep_done = 0;
__device__ unsigned passed    = 0;

// ---- packed f32x2 helpers ----
typedef unsigned long long u64;
__device__ __forceinline__ u64 pack2(float lo, float hi) {
    u64 r; asm("mov.b64 %0, {%1, %2};" : "=l"(r) : "f"(lo), "f"(hi)); return r;
}
__device__ __forceinline__ void unpack2(u64 v, float& lo, float& hi) {
    asm("mov.b64 {%0, %1}, %2;" : "=f"(lo), "=f"(hi) : "l"(v));
}
__device__ __forceinline__ u64 mul2(u64 a, u64 b) {
    u64 r; asm("mul.rn.f32x2 %0, %1, %2;" : "=l"(r) : "l"(a), "l"(b)); return r;
}
__device__ __forceinline__ u64 add2(u64 a, u64 b) {
    u64 r; asm("add.rn.f32x2 %0, %1, %2;" : "=l"(r) : "l"(a), "l"(b)); return r;
}
__device__ __forceinline__ u64 fma2(u64 a, u64 b, u64 c) {
    u64 r; asm("fma.rn.f32x2 %0, %1, %2, %3;" : "=l"(r) : "l"(a), "l"(b), "l"(c)); return r;
}

// Raw reciprocal divide: MUFU.RCP + FMUL (~1 ulp quotient).
__device__ __forceinline__ float fast_div(float x, float y) {
    float r0;
    asm("rcp.approx.f32 %0, %1;" : "=f"(r0) : "f"(y));
    return x * r0;
}

// Fast cos: exact RNE(x/2pi) via magic-number fma, 1-word reduction, MUFU cos.
__device__ __forceinline__ float fast_cos(float x) {
    const float MAGIC = 12582912.0f;                 // 1.5 * 2^23
    float q = fmaf(x, 0.15915494309189535f, MAGIC) - MAGIC;
    float r = fmaf(q, -6.28318548202514648f, x);     // C1 = fp32(2*pi)
    return __cosf(r);
}

// Compute one SD element (global index e < SD_TOTAL).
__device__ __forceinline__ void sd_element(int e, const float* __restrict__ d,
                                           const float* __restrict__ dc)
{
    const int b = e / SD_STRIDE;
    const int r = e - b * SD_STRIDE;
    const int m = r >> 6;
    const int k = r & 63;
    const int j = (k + m) & 63;

    const float* db  = d  + b * 4096;
    const float* dcb = dc + b * 4096;

    float djk = db[j * 64 + k];
    float dkj = db[k * 64 + j];
    float gjk = __expf(-4.0f * djk * djk) * dcb[j * 64 + k];
    float gkj = __expf(-4.0f * dkj * dkj) * dcb[k * 64 + j];

    const float w = (m == 0) ? 0.125f : ((m == 32) ? 0.5f : 1.0f);
    SD_buf[e] = w * (gjk + gkj);
}

__global__ __launch_bounds__(256, 7)
void angular_fused(const float* __restrict__ dc,
                   const float* __restrict__ d,
                   const float* __restrict__ coords,
                   float* __restrict__ out)
{
    const int bi = blockIdx.x;      // 0..1023
    const int b  = bi >> 6;
    const int i  = bi & 63;

    __shared__ float4 s_v4[2 * M_DIM];      // replicated: [j] == [j+64]
    __shared__ float  s_F[2 * M_DIM];       // replicated
    __shared__ u64    s_red[8][3];

    const int tid = threadIdx.x;

    // ---- Phase 1: this block's 33 SD elements (threads 0..32) ----
    if (tid < 33) sd_element(bi * 33 + tid, d, dc);

    // ---- Prologue (overlaps phase 1): only harness inputs ----
    if (tid >= 64 && tid < 192) {
        const int p = tid - 64;         // 0..127 = copy*64 + j
        const int j = p & 63;
        const float* cb = coords + (size_t)b * 192;
        float cx = cb[i * 3 + 0];
        float cy = cb[i * 3 + 1];
        float cz = cb[i * 3 + 2];
        float4 v;
        v.x = cb[j * 3 + 0] - cx;
        v.y = cb[j * 3 + 1] - cy;
        v.z = cb[j * 3 + 2] - cz;
        v.w = d[(size_t)b * 4096 + i * 64 + j];
        float F = dc[(size_t)b * 4096 + i * 64 + j] * __expf(-4.0f * v.w * v.w);
        s_v4[p] = v;
        s_F[p]  = F;
    }
    __syncthreads();

    // ---- Grid barrier: all blocks' SD stores visible before any SD read ----
    if (tid == 0) {
        __threadfence();                          // release SD stores
        atomicAdd(&prep_done, 1u);
        while (*(volatile unsigned*)&prep_done != GRID_N) __nanosleep(32);
    }
    __syncthreads();
    __threadfence();                              // acquire SD stores

    const int k = tid & 63;
    const int g = tid >> 6;    // 0..3

    const float4 vk = s_v4[k];
    const float  Fk = s_F[k];
    // Bases for immediate-offset addressing: iteration t uses index base + 4t.
    const float4* vbase = s_v4 + (k + g + 1);     // j = k+g+1+4t  (max 95 < 128)
    const float*  fbase = s_F  + (k + g + 1);
    const float*  sbase = SD_buf + b * SD_STRIDE + ((g + 1) << 6) + k;  // +256*t

    const u64 ONE2 = 0x3F8000003F800000ull;  // ( 1.0f,  1.0f)
    const u64 PM1  = 0xBF8000003F800000ull;  // ( 1.0f, -1.0f)  lo=+1, hi=-1
    u64 acc2 = 0, acc4 = 0, acc8 = 0;        // (lambda=+1, lambda=-1) per zeta

    // Diagonal (j == k) FIRST: g==0 warps only, weight x4 on SD row 0
    // (0.125 baked in; 0.5*(2 g_kk) = exactly one ordered term).
    if (g == 0) {
        float  Sv = 4.0f * SD_buf[b * SD_STRIDE + k];
        float dot = vk.x * vk.x + vk.y * vk.y + vk.z * vk.z;
        float den = vk.w * vk.w + 1e-5f;
        float c   = fast_cos(fast_div(dot, den));
        float w   = Fk * Sv;                 // Fj == Fk on the diagonal

        u64 tpm = fma2(pack2(c, c), PM1, ONE2);
        u64 t2  = mul2(tpm, tpm);
        u64 t4  = mul2(t2, t2);
        u64 t8  = mul2(t4, t4);
        u64 wp  = pack2(w, w);

        acc2 = fma2(t2, wp, acc2);
        acc4 = fma2(t4, wp, acc4);
        acc8 = fma2(t8, wp, acc8);
    }

    // 8 pair iterations, m = 4t+g+1 (m = 1..32 across groups), in two
    // half-batches with Sv prefetched (MLP-4 LDG) and vj/Fj LDS
    // double-buffered one iteration ahead.
    float4 vj_n = vbase[0];
    float  Fj_n = fbase[0];

    #pragma unroll
    for (int half = 0; half < 2; half++) {
        float Svp[4];
        #pragma unroll
        for (int u = 0; u < 4; u++)
            Svp[u] = sbase[(half * 4 + u) << 8];   // LDG [base + 1024B*t]

        #pragma unroll
        for (int u = 0; u < 4; u++) {
            const int t = half * 4 + u;
            float4 vj = vj_n;
            float  Fj = Fj_n;
            if (t < 7) {
                vj_n = vbase[(t + 1) << 2];        // LDS.128 next iter
                Fj_n = fbase[(t + 1) << 2];        // LDS.32  next iter
            }

            float dot = vj.x * vk.x + vj.y * vk.y + vj.z * vk.z;
            float den = vj.w * vk.w + 1e-5f;
            float c   = fast_cos(fast_div(dot, den));
            float w   = Fj * Svp[u];               // Fk applied after the loop

            u64 tpm = fma2(pack2(c, c), PM1, ONE2);   // (1+c, 1-c)
            u64 t2  = mul2(tpm, tpm);
            u64 t4  = mul2(t2, t2);
            u64 t8  = mul2(t4, t4);
            u64 wp  = pack2(w, w);

            acc2 = fma2(t2, wp, acc2);
            acc4 = fma2(t4, wp, acc4);
            acc8 = fma2(t8, wp, acc8);
        }
    }

    // Apply hoisted Fk (packed) before reduction (Fk varies by k)
    {
        u64 Fkp = pack2(Fk, Fk);
        acc2 = mul2(acc2, Fkp);
        acc4 = mul2(acc4, Fkp);
        acc8 = mul2(acc8, Fkp);
    }

    // Packed warp reduction (64-bit shuffles + add.rn.f32x2)
    #pragma unroll
    for (int off = 16; off > 0; off >>= 1) {
        acc2 = add2(acc2, __shfl_down_sync(0xffffffffu, acc2, off));
        acc4 = add2(acc4, __shfl_down_sync(0xffffffffu, acc4, off));
        acc8 = add2(acc8, __shfl_down_sync(0xffffffffu, acc8, off));
    }

    const int wid  = tid >> 5;
    const int lane = tid & 31;
    if (lane == 0) {
        s_red[wid][0] = acc2; s_red[wid][1] = acc4; s_red[wid][2] = acc8;
    }
    __syncthreads();

    if (tid < 3) {
        u64 s = s_red[0][tid];
        #pragma unroll
        for (int w = 1; w < 8; w++) s = add2(s, s_red[w][tid]);
        float plus, minus;
        unpack2(s, plus, minus);
        // scale = 2^(1 - zeta), zeta = [2,4,8]
        const float scale = (tid == 0) ? 0.5f : ((tid == 1) ? 0.125f : 0.0078125f);
        float* o = out + (size_t)bi * 6;
        o[tid]     = plus  * scale;   // lambda = +1
        o[3 + tid] = minus * scale;   // lambda = -1
    }
    __syncthreads();

    // ---- Replay reset: last block to finish clears both counters. All
    // blocks have passed the spin (prep_done no longer read this run), so
    // the plain stores race with nothing.
    if (tid == 0) {
        unsigned old = atomicAdd(&passed, 1u);
        if (old == GRID_N - 1) {
            prep_done = 0;
            passed    = 0;
            __threadfence();
        }
    }
}

extern "C" void kernel_launch(void* const* d_in, const int* in_sizes, int n_in,
                              void* d_out, int out_size)
{
    const float* d_cutoff = (const float*)d_in[0];
    const float* d        = (const float*)d_in[1];
    const float* coords   = (const float*)d_in[2];
    float* out = (float*)d_out;

    angular_fused<<<GRID_N, 256>>>(d_cutoff, d, coords, out);
}

// round 16
// speedup vs baseline: 1.4048x; 1.4048x over previous
#include <cuda_runtime.h>

// AngularSymmetry B=16, M=64.
//  prep (16 blocks x 1024, one block per batch): fully coalesced
//    smem-transpose build of SD[b][m][k] = wgt*(g[(k+m)%64][k]+g[k][(k+m)%64]),
//    m=0..32; g = __expf(-4 d^2)*dc; wgt = 0.125 (m=0), 0.5 (m=32), 1 else.
//  main (1024 blocks x 256, PDL-overlapped): block=(b,i).
//    m = 4t+g+1 (t=0..7, g=tid>>6); diagonal on g==0 (SD row0 x4) first.
//    Sv LDG MLP-4 batches; vj/Fj LDS double-buffered; raw rcp.approx divide;
//    1-word Cody-Waite cos; packed f32x2 powers/accumulators/reduction.

#define B_DIM 16
#define M_DIM 64
#define SD_STRIDE (33 * 64)     // 2112 floats per batch
#define SD_TOTAL (B_DIM * SD_STRIDE)

__device__ float SD_buf[SD_TOTAL];

__global__ __launch_bounds__(1024)
void prep_kernel(const float* __restrict__ d, const float* __restrict__ dc)
{
    __shared__ float sg[M_DIM * 65];          // stride-65: conflict-free transpose
    const int b   = blockIdx.x;
    const int tid = threadIdx.x;              // 0..1023
    const float* db  = d  + b * 4096;
    const float* dcb = dc + b * 4096;

    #pragma unroll
    for (int c = 0; c < 4; c++) {
        int e = tid + c * 1024;               // coalesced over 4096
        int j = e >> 6, k = e & 63;
        float dv = db[e];
        sg[j * 65 + k] = __expf(-4.0f * dv * dv) * dcb[e];
    }
    __syncthreads();

    #pragma unroll
    for (int c = 0; c < 3; c++) {
        int e = tid + c * 1024;
        if (e < SD_STRIDE) {
            int m = e >> 6, k = e & 63;
            int j = (k + m) & 63;
            float w = (m == 0) ? 0.125f : ((m == 32) ? 0.5f : 1.0f);
            SD_buf[b * SD_STRIDE + e] = w * (sg[j * 65 + k] + sg[k * 65 + j]);
        }
    }
}

// ---- packed f32x2 helpers ----
typedef unsigned long long u64;
__device__ __forceinline__ u64 pack2(float lo, float hi) {
    u64 r; asm("mov.b64 %0, {%1, %2};" : "=l"(r) : "f"(lo), "f"(hi)); return r;
}
__device__ __forceinline__ void unpack2(u64 v, float& lo, float& hi) {
    asm("mov.b64 {%0, %1}, %2;" : "=f"(lo), "=f"(hi) : "l"(v));
}
__device__ __forceinline__ u64 mul2(u64 a, u64 b) {
    u64 r; asm("mul.rn.f32x2 %0, %1, %2;" : "=l"(r) : "l"(a), "l"(b)); return r;
}
__device__ __forceinline__ u64 add2(u64 a, u64 b) {
    u64 r; asm("add.rn.f32x2 %0, %1, %2;" : "=l"(r) : "l"(a), "l"(b)); return r;
}
__device__ __forceinline__ u64 fma2(u64 a, u64 b, u64 c) {
    u64 r; asm("fma.rn.f32x2 %0, %1, %2, %3;" : "=l"(r) : "l"(a), "l"(b), "l"(c)); return r;
}

// Raw reciprocal divide: MUFU.RCP + FMUL (~1 ulp quotient).
__device__ __forceinline__ float fast_div(float x, float y) {
    float r0;
    asm("rcp.approx.f32 %0, %1;" : "=f"(r0) : "f"(y));
    return x * r0;
}

// Fast cos: exact RNE(x/2pi) via magic-number fma, 1-word reduction, MUFU cos.
__device__ __forceinline__ float fast_cos(float x) {
    const float MAGIC = 12582912.0f;                 // 1.5 * 2^23
    float q = fmaf(x, 0.15915494309189535f, MAGIC) - MAGIC;
    float r = fmaf(q, -6.28318548202514648f, x);     // C1 = fp32(2*pi)
    return __cosf(r);
}

__global__ __launch_bounds__(256, 7)
void angular_main(const float* __restrict__ dc,
                  const float* __restrict__ d,
                  const float* __restrict__ coords,
                  float* __restrict__ out)
{
    const int bi = blockIdx.x;      // 0..1023
    const int b  = bi >> 6;
    const int i  = bi & 63;

    __shared__ float4 s_v4[2 * M_DIM];      // replicated: [j] == [j+64]
    __shared__ float  s_F[2 * M_DIM];       // replicated
    __shared__ u64    s_red[8][3];

    const int tid = threadIdx.x;

    // Prologue: only harness inputs (safe before prep completes under PDL).
    if (tid < 128) {
        const int j = tid & 63;
        const float* cb = coords + (size_t)b * 192;
        float cx = cb[i * 3 + 0];
        float cy = cb[i * 3 + 1];
        float cz = cb[i * 3 + 2];
        float4 v;
        v.x = cb[j * 3 + 0] - cx;
        v.y = cb[j * 3 + 1] - cy;
        v.z = cb[j * 3 + 2] - cz;
        v.w = d[(size_t)b * 4096 + i * 64 + j];
        float F = dc[(size_t)b * 4096 + i * 64 + j] * __expf(-4.0f * v.w * v.w);
        s_v4[tid] = v;          // tid = copy*64 + j
        s_F[tid]  = F;
    }
    __syncthreads();

    // PDL fence: prep's SD_buf writes must be visible past this point.
    cudaGridDependencySynchronize();

    const int k = tid & 63;
    const int g = tid >> 6;    // 0..3

    const float4 vk = s_v4[k];
    const float  Fk = s_F[k];
    // Bases for immediate-offset addressing: iteration t uses index base + 4t.
    const float4* vbase = s_v4 + (k + g + 1);     // j = k+g+1+4t  (max 95 < 128)
    const float*  fbase = s_F  + (k + g + 1);
    const float*  sbase = SD_buf + b * SD_STRIDE + ((g + 1) << 6) + k;  // +256*t

    const u64 ONE2 = 0x3F8000003F800000ull;  // ( 1.0f,  1.0f)
    const u64 PM1  = 0xBF8000003F800000ull;  // ( 1.0f, -1.0f)  lo=+1, hi=-1
    u64 acc2 = 0, acc4 = 0, acc8 = 0;        // (lambda=+1, lambda=-1) per zeta

    // Diagonal (j == k) FIRST: g==0 warps only, weight x4 on SD row 0
    // (0.125 baked in; 0.5*(2 g_kk) = exactly one ordered term).
    if (g == 0) {
        float  Sv = 4.0f * SD_buf[b * SD_STRIDE + k];
        float dot = vk.x * vk.x + vk.y * vk.y + vk.z * vk.z;
        float den = vk.w * vk.w + 1e-5f;
        float c   = fast_cos(fast_div(dot, den));
        float w   = Fk * Sv;                 // Fj == Fk on the diagonal

        u64 tpm = fma2(pack2(c, c), PM1, ONE2);
        u64 t2  = mul2(tpm, tpm);
        u64 t4  = mul2(t2, t2);
        u64 t8  = mul2(t4, t4);
        u64 wp  = pack2(w, w);

        acc2 = fma2(t2, wp, acc2);
        acc4 = fma2(t4, wp, acc4);
        acc8 = fma2(t8, wp, acc8);
    }

    // 8 pair iterations, m = 4t+g+1 (m = 1..32 across groups), in two
    // half-batches with Sv prefetched (MLP-4 LDG) and vj/Fj LDS
    // double-buffered one iteration ahead.
    float4 vj_n = vbase[0];
    float  Fj_n = fbase[0];

    #pragma unroll
    for (int half = 0; half < 2; half++) {
        float Svp[4];
        #pragma unroll
        for (int u = 0; u < 4; u++)
            Svp[u] = sbase[(half * 4 + u) << 8];   // LDG [base + 1024B*t]

        #pragma unroll
        for (int u = 0; u < 4; u++) {
            const int t = half * 4 + u;
            float4 vj = vj_n;
            float  Fj = Fj_n;
            if (t < 7) {
                vj_n = vbase[(t + 1) << 2];        // LDS.128 next iter
                Fj_n = fbase[(t + 1) << 2];        // LDS.32  next iter
            }

            float dot = vj.x * vk.x + vj.y * vk.y + vj.z * vk.z;
            float den = vj.w * vk.w + 1e-5f;
            float c   = fast_cos(fast_div(dot, den));
            float w   = Fj * Svp[u];               // Fk applied after the loop

            u64 tpm = fma2(pack2(c, c), PM1, ONE2);   // (1+c, 1-c)
            u64 t2  = mul2(tpm, tpm);
            u64 t4  = mul2(t2, t2);
            u64 t8  = mul2(t4, t4);
            u64 wp  = pack2(w, w);

            acc2 = fma2(t2, wp, acc2);
            acc4 = fma2(t4, wp, acc4);
            acc8 = fma2(t8, wp, acc8);
        }
    }

    // Apply hoisted Fk (packed) before reduction (Fk varies by k)
    {
        u64 Fkp = pack2(Fk, Fk);
        acc2 = mul2(acc2, Fkp);
        acc4 = mul2(acc4, Fkp);
        acc8 = mul2(acc8, Fkp);
    }

    // Packed warp reduction (64-bit shuffles + add.rn.f32x2)
    #pragma unroll
    for (int off = 16; off > 0; off >>= 1) {
        acc2 = add2(acc2, __shfl_down_sync(0xffffffffu, acc2, off));
        acc4 = add2(acc4, __shfl_down_sync(0xffffffffu, acc4, off));
        acc8 = add2(acc8, __shfl_down_sync(0xffffffffu, acc8, off));
    }

    const int wid  = tid >> 5;
    const int lane = tid & 31;
    if (lane == 0) {
        s_red[wid][0] = acc2; s_red[wid][1] = acc4; s_red[wid][2] = acc8;
    }
    __syncthreads();

    if (tid < 3) {
        u64 s = s_red[0][tid];
        #pragma unroll
        for (int w = 1; w < 8; w++) s = add2(s, s_red[w][tid]);
        float plus, minus;
        unpack2(s, plus, minus);
        // scale = 2^(1 - zeta), zeta = [2,4,8]
        const float scale = (tid == 0) ? 0.5f : ((tid == 1) ? 0.125f : 0.0078125f);
        float* o = out + (size_t)bi * 6;
        o[tid]     = plus  * scale;   // lambda = +1
        o[3 + tid] = minus * scale;   // lambda = -1
    }
}

extern "C" void kernel_launch(void* const* d_in, const int* in_sizes, int n_in,
                              void* d_out, int out_size)
{
    const float* d_cutoff = (const float*)d_in[0];
    const float* d        = (const float*)d_in[1];
    const float* coords   = (const float*)d_in[2];
    float* out = (float*)d_out;

    prep_kernel<<<B_DIM, 1024>>>(d, d_cutoff);

    // Main launched with programmatic stream serialization (PDL): may start
    // while prep is still in flight; the grid-dependency sync inside the
    // kernel orders SD_buf reads after prep completion.
    cudaLaunchConfig_t cfg = {};
    cfg.gridDim  = dim3(1024, 1, 1);
    cfg.blockDim = dim3(256, 1, 1);
    cfg.dynamicSmemBytes = 0;
    cfg.stream = 0;
    cudaLaunchAttribute attr[1];
    attr[0].id = cudaLaunchAttributeProgrammaticStreamSerialization;
    attr[0].val.programmaticStreamSerializationAllowed = 1;
    cfg.attrs = attr;
    cfg.numAttrs = 1;
    cudaLaunchKernelEx(&cfg, angular_main, d_cutoff, d, coords, out);
}